// round 16
// baseline (speedup 1.0000x reference)
#include <cuda_runtime.h>
#include <cuda_fp16.h>
#include <stdint.h>

#define B_ 4
#define T_ 4096
#define E_ 1024
#define D_ 64
#define M_ (B_*T_)
#define ROWS_FULL 112
#define GX 37              // proj: per batch 36 x 112 rows + 1 x 64 rows

typedef unsigned short u16;
typedef unsigned int   u32;

__device__ __align__(16) u16 g_q16[M_*D_];
__device__ __align__(16) u16 g_k16[M_*D_];
__device__ __align__(16) u16 g_v16[M_*D_];

__device__ __forceinline__ float ex2f(float x){
    float y; asm("ex2.approx.f32 %0, %1;" : "=f"(y) : "f"(x)); return y;
}
__device__ __forceinline__ u32 smaddr(const void* p){
    u32 a; asm("{ .reg .u64 t; cvta.to.shared.u64 t, %1; cvt.u32.u64 %0, t; }" : "=r"(a) : "l"(p));
    return a;
}
__device__ __forceinline__ void ldsm4(u32 r[4], u32 a){
    asm volatile("ldmatrix.sync.aligned.m8n8.x4.shared.b16 {%0,%1,%2,%3}, [%4];"
        : "=r"(r[0]),"=r"(r[1]),"=r"(r[2]),"=r"(r[3]) : "r"(a));
}
__device__ __forceinline__ void ldsm4t(u32 r[4], u32 a){
    asm volatile("ldmatrix.sync.aligned.m8n8.x4.trans.shared.b16 {%0,%1,%2,%3}, [%4];"
        : "=r"(r[0]),"=r"(r[1]),"=r"(r[2]),"=r"(r[3]) : "r"(a));
}
__device__ __forceinline__ void mmaf(float c[4], const u32 a[4], u32 b0, u32 b1){
    asm volatile("mma.sync.aligned.m16n8k16.row.col.f32.f16.f16.f32 "
        "{%0,%1,%2,%3}, {%4,%5,%6,%7}, {%8,%9}, {%0,%1,%2,%3};"
        : "+f"(c[0]),"+f"(c[1]),"+f"(c[2]),"+f"(c[3])
        : "r"(a[0]),"r"(a[1]),"r"(a[2]),"r"(a[3]), "r"(b0),"r"(b1));
}
__device__ __forceinline__ u32 pack2h(float x0, float x1){
    __half2 h = __floats2half2_rn(x0, x1);
    return *reinterpret_cast<u32*>(&h);
}
#define CP16(dst, src) asm volatile("cp.async.cg.shared.global [%0], [%1], 16;" :: "r"(dst), "l"(src))
#define CPCOMMIT()     asm volatile("cp.async.commit_group;" ::: "memory")
#define CPWAIT(n)      asm volatile("cp.async.wait_group %0;" :: "n"(n) : "memory")

// ---------------------------------------------------------------------------
// Kernel 1: fused QKV projection (unchanged from R15 — passing).
// W converted fp32->fp16 inline; natural [e][d] smem layout + ldsm4t.
// grid (37,4), block 448.
// ---------------------------------------------------------------------------
#define PSTR 72
#define X_STAGE (ROWS_FULL*PSTR)
#define W_STAGE (3*64*PSTR)

__global__ __launch_bounds__(448) void proj(
    const float* __restrict__ x,
    const float* __restrict__ Wq, const float* __restrict__ Wk, const float* __restrict__ Wv)
{
    extern __shared__ u16 sp[];
    u16* Xs0 = sp;
    u16* Xs1 = sp + X_STAGE;
    u16* Ws0 = sp + 2*X_STAGE;
    u16* Ws1 = Ws0 + W_STAGE;

    const int tid  = threadIdx.x;
    const int lane = tid & 31;
    const int wid  = tid >> 5;
    const int nhalf = (wid >= 7) ? 1 : 0;
    const int qw    = wid - nhalf*7;
    const int m0    = blockIdx.y * T_ + blockIdx.x * ROWS_FULL;
    const int nrows = (blockIdx.x == GX-1) ? 64 : ROWS_FULL;
    const int wm    = qw * 16;

    float acc[3][4][4];
    #pragma unroll
    for (int w = 0; w < 3; w++)
        #pragma unroll
        for (int j = 0; j < 4; j++)
            #pragma unroll
            for (int q = 0; q < 4; q++) acc[w][j][q] = 0.f;

    const int arow = wm + (lane & 15);
    const int acol = ((lane >> 4) << 3);
    const int trow = (lane & 15);
    const int tcol = ((lane >> 4) << 3);

    float4 wr[7];
    auto loadW = [&](int it){
        #pragma unroll
        for (int t = 0; t < 7; t++) {
            int id = tid + t*448;
            if (id < 3072) {
                int w  = id >> 10;
                int e  = (id & 1023) >> 4;
                int c4 = id & 15;
                const float* W = (w == 0) ? Wq : ((w == 1) ? Wk : Wv);
                wr[t] = *reinterpret_cast<const float4*>(
                    &W[(size_t)(it*64 + e) * D_ + c4*4]);
            }
        }
    };
    auto storeW = [&](u16* Wst){
        #pragma unroll
        for (int t = 0; t < 7; t++) {
            int id = tid + t*448;
            if (id < 3072) {
                int w  = id >> 10;
                int e  = (id & 1023) >> 4;
                int c4 = id & 15;
                u32 h0 = pack2h(wr[t].x, wr[t].y);
                u32 h1 = pack2h(wr[t].z, wr[t].w);
                *reinterpret_cast<uint2*>(&Wst[w*64*PSTR + e*PSTR + c4*4]) =
                    make_uint2(h0, h1);
            }
        }
    };

    float4 xr[4];
    #pragma unroll
    for (int t = 0; t < 4; t++) {
        int id = tid + t * 448;
        int r = id >> 4, c4 = id & 15;
        int grow = m0 + r; if (grow > M_-1) grow = M_-1;
        xr[t] = *reinterpret_cast<const float4*>(&x[(size_t)grow * E_ + c4*4]);
    }
    loadW(0);

    for (int it = 0; it < E_/64; it++) {
        u16* Xst = (it & 1) ? Xs1 : Xs0;
        u16* Wst = (it & 1) ? Ws1 : Ws0;

        #pragma unroll
        for (int t = 0; t < 4; t++) {
            int id = tid + t * 448;
            int r = id >> 4, c4 = id & 15;
            u32 h0 = pack2h(xr[t].x, xr[t].y);
            u32 h1 = pack2h(xr[t].z, xr[t].w);
            *reinterpret_cast<uint2*>(&Xst[r*PSTR + c4*4]) = make_uint2(h0, h1);
        }
        storeW(Wst);

        if (it + 1 < E_/64) {
            #pragma unroll
            for (int t = 0; t < 4; t++) {
                int id = tid + t * 448;
                int r = id >> 4, c4 = id & 15;
                int grow = m0 + r; if (grow > M_-1) grow = M_-1;
                xr[t] = *reinterpret_cast<const float4*>(
                    &x[(size_t)grow * E_ + (it+1)*64 + c4*4]);
            }
            loadW(it + 1);
        }
        __syncthreads();

        const u32 sX = smaddr(Xst);
        const u32 sW = smaddr(Wst);
        #pragma unroll
        for (int k4 = 0; k4 < 4; k4++) {
            u32 ah[4];
            ldsm4(ah, sX + 2*(arow*PSTR + k4*16 + acol));
            #pragma unroll
            for (int w = 0; w < 3; w++) {
                #pragma unroll
                for (int npl = 0; npl < 2; npl++) {
                    int np = nhalf*2 + npl;
                    u32 bh[4];
                    u32 off = sW + 2*(u32)(w*64*PSTR + (k4*16 + trow)*PSTR + np*16 + tcol);
                    ldsm4t(bh, off);
                    mmaf(acc[w][2*npl],   ah, bh[0], bh[1]);
                    mmaf(acc[w][2*npl+1], ah, bh[2], bh[3]);
                }
            }
        }
        __syncthreads();
    }

    const float qs = 0.125f * 1.4426950408889634f;
    const int lrow = wm + (lane >> 2);
    const int r0 = m0 + lrow;
    const int cc = (lane & 3) * 2;
    #pragma unroll
    for (int w = 0; w < 3; w++) {
        u16* gh = (w == 0) ? g_q16 : ((w == 1) ? g_k16 : g_v16);
        const float s = (w == 0) ? qs : 1.0f;
        #pragma unroll
        for (int jl = 0; jl < 4; jl++) {
            int jg = 4*nhalf + jl;
            if (lrow < nrows)
                *reinterpret_cast<u32*>(&gh[(size_t)r0*D_ + jg*8 + cc]) =
                    pack2h(acc[w][jl][0]*s, acc[w][jl][1]*s);
            if (lrow + 8 < nrows)
                *reinterpret_cast<u32*>(&gh[(size_t)(r0+8)*D_ + jg*8 + cc]) =
                    pack2h(acc[w][jl][2]*s, acc[w][jl][3]*s);
        }
    }
}

// ---------------------------------------------------------------------------
// Kernel 2: fp16 HMMA flash attention, HALF-SIZE CTA for 2 CTAs/SM.
// 64 q-rows/CTA, grid (64,4) = 256 CTAs, block 256 = 4 qg(16 rows) x 2 khalf.
// Co-resident CTAs share no barrier -> their MMA/MUFU phases overlap.
// 4-stage ring, 1 barrier/tile, Q parks in stage 3.
// ---------------------------------------------------------------------------
#define ASTR 72
#define KV_U16 (2*64*ASTR)   // u16 per stage (18432 B)
#define NSTG 4
#define LOG2_SHIFT 12.0f

__global__ __launch_bounds__(256, 2) void attn(float* __restrict__ out)
{
    extern __shared__ u16 sma[];   // 4 stages; reused as float Obuf at the end

    const int tid  = threadIdx.x;
    const int lane = tid & 31;
    const int wid  = tid >> 5;
    const int khalf = (wid >= 4) ? 1 : 0;   // key half (32 keys)
    const int qg    = wid - khalf*4;        // q-row group (16 rows)
    const int bq0   = blockIdx.y * T_ + blockIdx.x * 64;
    const int b     = blockIdx.y;

    const size_t bbase = (size_t)b * T_ * D_;
    auto issueKV = [&](int kt, int s){
        const u32 stb = smaddr(sma + s*KV_U16);
        const size_t kbase = bbase + (size_t)kt*64*D_;
        #pragma unroll
        for (int t = 0; t < 4; t++) {
            int id = tid + t*256;        // 1024 chunks exactly
            int a   = id >> 9;           // 0 = K, 1 = V
            int rem = id & 511;
            int r  = rem >> 3;
            int ch = rem & 7;
            const u16* g = a ? g_v16 : g_k16;
            const u16* src = g + kbase + (size_t)r*D_ + ch*8;
            u32 dst = stb + 2*(u32)(a*64*ASTR + r*ASTR + ch*8);
            CP16(dst, src);
        }
    };

    // Prologue: tiles 0,1,2 into stages 0,1,2.
    issueKV(0, 0); CPCOMMIT();
    issueKV(1, 1); CPCOMMIT();
    issueKV(2, 2); CPCOMMIT();

    // Q parks in stage 3 (tile 3 only lands there after the first loop barrier).
    u16* Qsm = sma + 3*KV_U16;
    #pragma unroll
    for (int t = 0; t < 2; t++) {
        int id = tid + t * 256;          // 64 rows x 8 chunks = 512 exactly
        int r = id >> 3, cc = id & 7;
        *reinterpret_cast<uint4*>(&Qsm[r*ASTR + cc*8]) =
            *reinterpret_cast<const uint4*>(&g_q16[(size_t)(bq0 + r)*D_ + cc*8]);
    }
    __syncthreads();

    const int acol = ((lane >> 4) << 3);
    const int arow = qg*16 + (lane & 15);
    u32 qf[4][4];
    {
        const u32 sQ = smaddr(Qsm);
        #pragma unroll
        for (int k4 = 0; k4 < 4; k4++)
            ldsm4(qf[k4], sQ + 2*(arow*ASTR + k4*16 + acol));
    }

    const int brow = (lane & 7) + ((lane >> 4) << 3);
    const int bcol = (lane & 8);
    const int vrow = (lane & 15);
    const int vcol = ((lane >> 4) << 3);
    const int kofs = khalf * 32;

    float o[8][4];
    #pragma unroll
    for (int j = 0; j < 8; j++)
        #pragma unroll
        for (int q = 0; q < 4; q++) o[j][q] = 0.f;
    float rs0 = 0.f, rs1 = 0.f;

    const int nT = T_/64;
    for (int kt = 0; kt < nT; kt++) {
        const int st = kt & 3;
        if (kt < nT - 2)      { CPWAIT(2); }
        else if (kt == nT-2)  { CPWAIT(1); }
        else                  { CPWAIT(0); }
        __syncthreads();
        if (kt + 3 < nT) { issueKV(kt + 3, (kt + 3) & 3); CPCOMMIT(); }

        const u32 stb = smaddr(sma + st*KV_U16);
        const u32 sK = stb;
        const u32 sV = stb + 2*(64*ASTR);

        // ---- S = Q @ K^T (this warp's 32-key half) ----
        float sc[4][4];
        #pragma unroll
        for (int j = 0; j < 4; j++)
            #pragma unroll
            for (int q = 0; q < 4; q++) sc[j][q] = 0.f;

        #pragma unroll
        for (int k4 = 0; k4 < 4; k4++) {
            #pragma unroll
            for (int np = 0; np < 2; np++) {
                u32 bh[4];
                ldsm4(bh, sK + 2*(u32)((kofs + np*16 + brow)*ASTR + k4*16 + bcol));
                mmaf(sc[2*np],   qf[k4], bh[0], bh[1]);
                mmaf(sc[2*np+1], qf[k4], bh[2], bh[3]);
            }
        }

        // ---- exp2 (shifted), partial row sums, pack P ----
        #pragma unroll
        for (int j = 0; j < 4; j++) {
            #pragma unroll
            for (int q = 0; q < 4; q++) sc[j][q] = ex2f(sc[j][q] - LOG2_SHIFT);
            rs0 += sc[j][0] + sc[j][1];
            rs1 += sc[j][2] + sc[j][3];
        }
        u32 pf[2][4];
        #pragma unroll
        for (int k2 = 0; k2 < 2; k2++) {
            pf[k2][0] = pack2h(sc[2*k2][0],   sc[2*k2][1]);
            pf[k2][1] = pack2h(sc[2*k2][2],   sc[2*k2][3]);
            pf[k2][2] = pack2h(sc[2*k2+1][0], sc[2*k2+1][1]);
            pf[k2][3] = pack2h(sc[2*k2+1][2], sc[2*k2+1][3]);
        }

        // ---- O += P @ V (over this warp's 32 keys) ----
        #pragma unroll
        for (int k2 = 0; k2 < 2; k2++) {
            #pragma unroll
            for (int np = 0; np < 4; np++) {
                u32 bh[4];
                ldsm4t(bh, sV + 2*(u32)((kofs + k2*16 + vrow)*ASTR + np*16 + vcol));
                mmaf(o[2*np],   pf[k2], bh[0], bh[1]);
                mmaf(o[2*np+1], pf[k2], bh[2], bh[3]);
            }
        }
    }

    // ---- combine the two key-halves ----
    rs0 += __shfl_xor_sync(0xffffffffu, rs0, 1);
    rs0 += __shfl_xor_sync(0xffffffffu, rs0, 2);
    rs1 += __shfl_xor_sync(0xffffffffu, rs1, 1);
    rs1 += __shfl_xor_sync(0xffffffffu, rs1, 2);

    __syncthreads();   // all stage reads done before smem reuse as Obuf
    float* Ob  = reinterpret_cast<float*>(sma);      // [64][68]
    float* rsb = Ob + 64*68;                         // [64]
    const int row0 = qg*16 + (lane >> 2);
    const int cc = (lane & 3) * 2;

    if (khalf == 0) {
        #pragma unroll
        for (int j = 0; j < 8; j++) {
            Ob[row0*68 + j*8 + cc]         = o[j][0];
            Ob[row0*68 + j*8 + cc + 1]     = o[j][1];
            Ob[(row0+8)*68 + j*8 + cc]     = o[j][2];
            Ob[(row0+8)*68 + j*8 + cc + 1] = o[j][3];
        }
        if ((lane & 3) == 0) { rsb[row0] = rs0; rsb[row0+8] = rs1; }
    }
    __syncthreads();
    if (khalf == 1) {
        const float i0 = 1.f / (rs0 + rsb[row0]);
        const float i1 = 1.f / (rs1 + rsb[row0+8]);
        const int r0 = bq0 + row0;
        #pragma unroll
        for (int j = 0; j < 8; j++) {
            float2 v0 = make_float2((o[j][0] + Ob[row0*68 + j*8 + cc]) * i0,
                                    (o[j][1] + Ob[row0*68 + j*8 + cc + 1]) * i0);
            float2 v1 = make_float2((o[j][2] + Ob[(row0+8)*68 + j*8 + cc]) * i1,
                                    (o[j][3] + Ob[(row0+8)*68 + j*8 + cc + 1]) * i1);
            *reinterpret_cast<float2*>(&out[(size_t)r0*D_ + j*8 + cc]) = v0;
            *reinterpret_cast<float2*>(&out[(size_t)(r0+8)*D_ + j*8 + cc]) = v1;
        }
    }
}

// ---------------------------------------------------------------------------

extern "C" void kernel_launch(void* const* d_in, const int* in_sizes, int n_in,
                              void* d_out, int out_size)
{
    const float* x  = (const float*)d_in[0];
    const float* Wq = (const float*)d_in[1];
    const float* Wk = (const float*)d_in[2];
    const float* Wv = (const float*)d_in[3];
    float* out = (float*)d_out;

    const int proj_smem = (2*X_STAGE + 2*W_STAGE) * (int)sizeof(u16);   // 87552
    cudaFuncSetAttribute(proj, cudaFuncAttributeMaxDynamicSharedMemorySize, proj_smem);
    proj<<<dim3(GX, B_), 448, proj_smem>>>(x, Wq, Wk, Wv);

    const int attn_smem = NSTG*KV_U16 * (int)sizeof(u16);               // 73728
    cudaFuncSetAttribute(attn, cudaFuncAttributeMaxDynamicSharedMemorySize, attn_smem);
    attn<<<dim3(64, B_), 256, attn_smem>>>(out);
}

// round 17
// speedup vs baseline: 1.0214x; 1.0214x over previous
#include <cuda_runtime.h>
#include <cuda_fp16.h>
#include <stdint.h>

#define B_ 4
#define T_ 4096
#define E_ 1024
#define D_ 64
#define M_ (B_*T_)
#define ROWS_FULL 112
#define GX 37              // proj: per batch 36 x 112 rows + 1 x 64 rows

typedef unsigned short u16;
typedef unsigned int   u32;

__device__ __align__(16) u16 g_q16[M_*D_];
__device__ __align__(16) u16 g_k16[M_*D_];
__device__ __align__(16) u16 g_v16[M_*D_];

__device__ __forceinline__ float ex2f(float x){
    float y; asm("ex2.approx.f32 %0, %1;" : "=f"(y) : "f"(x)); return y;
}
__device__ __forceinline__ u32 smaddr(const void* p){
    u32 a; asm("{ .reg .u64 t; cvta.to.shared.u64 t, %1; cvt.u32.u64 %0, t; }" : "=r"(a) : "l"(p));
    return a;
}
__device__ __forceinline__ void ldsm4(u32 r[4], u32 a){
    asm volatile("ldmatrix.sync.aligned.m8n8.x4.shared.b16 {%0,%1,%2,%3}, [%4];"
        : "=r"(r[0]),"=r"(r[1]),"=r"(r[2]),"=r"(r[3]) : "r"(a));
}
__device__ __forceinline__ void ldsm4t(u32 r[4], u32 a){
    asm volatile("ldmatrix.sync.aligned.m8n8.x4.trans.shared.b16 {%0,%1,%2,%3}, [%4];"
        : "=r"(r[0]),"=r"(r[1]),"=r"(r[2]),"=r"(r[3]) : "r"(a));
}
__device__ __forceinline__ void mmaf(float c[4], const u32 a[4], u32 b0, u32 b1){
    asm volatile("mma.sync.aligned.m16n8k16.row.col.f32.f16.f16.f32 "
        "{%0,%1,%2,%3}, {%4,%5,%6,%7}, {%8,%9}, {%0,%1,%2,%3};"
        : "+f"(c[0]),"+f"(c[1]),"+f"(c[2]),"+f"(c[3])
        : "r"(a[0]),"r"(a[1]),"r"(a[2]),"r"(a[3]), "r"(b0),"r"(b1));
}
__device__ __forceinline__ u32 pack2h(float x0, float x1){
    __half2 h = __floats2half2_rn(x0, x1);
    return *reinterpret_cast<u32*>(&h);
}
#define CP16(dst, src) asm volatile("cp.async.cg.shared.global [%0], [%1], 16;" :: "r"(dst), "l"(src))
#define CPCOMMIT()     asm volatile("cp.async.commit_group;" ::: "memory")
#define CPWAIT(n)      asm volatile("cp.async.wait_group %0;" :: "n"(n) : "memory")

// ---------------------------------------------------------------------------
// Kernel 1: fused QKV projection (unchanged from R15 — passing).
// ---------------------------------------------------------------------------
#define PSTR 72
#define X_STAGE (ROWS_FULL*PSTR)
#define W_STAGE (3*64*PSTR)

__global__ __launch_bounds__(448) void proj(
    const float* __restrict__ x,
    const float* __restrict__ Wq, const float* __restrict__ Wk, const float* __restrict__ Wv)
{
    extern __shared__ u16 sp[];
    u16* Xs0 = sp;
    u16* Xs1 = sp + X_STAGE;
    u16* Ws0 = sp + 2*X_STAGE;
    u16* Ws1 = Ws0 + W_STAGE;

    const int tid  = threadIdx.x;
    const int lane = tid & 31;
    const int wid  = tid >> 5;
    const int nhalf = (wid >= 7) ? 1 : 0;
    const int qw    = wid - nhalf*7;
    const int m0    = blockIdx.y * T_ + blockIdx.x * ROWS_FULL;
    const int nrows = (blockIdx.x == GX-1) ? 64 : ROWS_FULL;
    const int wm    = qw * 16;

    float acc[3][4][4];
    #pragma unroll
    for (int w = 0; w < 3; w++)
        #pragma unroll
        for (int j = 0; j < 4; j++)
            #pragma unroll
            for (int q = 0; q < 4; q++) acc[w][j][q] = 0.f;

    const int arow = wm + (lane & 15);
    const int acol = ((lane >> 4) << 3);
    const int trow = (lane & 15);
    const int tcol = ((lane >> 4) << 3);

    float4 wr[7];
    auto loadW = [&](int it){
        #pragma unroll
        for (int t = 0; t < 7; t++) {
            int id = tid + t*448;
            if (id < 3072) {
                int w  = id >> 10;
                int e  = (id & 1023) >> 4;
                int c4 = id & 15;
                const float* W = (w == 0) ? Wq : ((w == 1) ? Wk : Wv);
                wr[t] = *reinterpret_cast<const float4*>(
                    &W[(size_t)(it*64 + e) * D_ + c4*4]);
            }
        }
    };
    auto storeW = [&](u16* Wst){
        #pragma unroll
        for (int t = 0; t < 7; t++) {
            int id = tid + t*448;
            if (id < 3072) {
                int w  = id >> 10;
                int e  = (id & 1023) >> 4;
                int c4 = id & 15;
                u32 h0 = pack2h(wr[t].x, wr[t].y);
                u32 h1 = pack2h(wr[t].z, wr[t].w);
                *reinterpret_cast<uint2*>(&Wst[w*64*PSTR + e*PSTR + c4*4]) =
                    make_uint2(h0, h1);
            }
        }
    };

    float4 xr[4];
    #pragma unroll
    for (int t = 0; t < 4; t++) {
        int id = tid + t * 448;
        int r = id >> 4, c4 = id & 15;
        int grow = m0 + r; if (grow > M_-1) grow = M_-1;
        xr[t] = *reinterpret_cast<const float4*>(&x[(size_t)grow * E_ + c4*4]);
    }
    loadW(0);

    for (int it = 0; it < E_/64; it++) {
        u16* Xst = (it & 1) ? Xs1 : Xs0;
        u16* Wst = (it & 1) ? Ws1 : Ws0;

        #pragma unroll
        for (int t = 0; t < 4; t++) {
            int id = tid + t * 448;
            int r = id >> 4, c4 = id & 15;
            u32 h0 = pack2h(xr[t].x, xr[t].y);
            u32 h1 = pack2h(xr[t].z, xr[t].w);
            *reinterpret_cast<uint2*>(&Xst[r*PSTR + c4*4]) = make_uint2(h0, h1);
        }
        storeW(Wst);

        if (it + 1 < E_/64) {
            #pragma unroll
            for (int t = 0; t < 4; t++) {
                int id = tid + t * 448;
                int r = id >> 4, c4 = id & 15;
                int grow = m0 + r; if (grow > M_-1) grow = M_-1;
                xr[t] = *reinterpret_cast<const float4*>(
                    &x[(size_t)grow * E_ + (it+1)*64 + c4*4]);
            }
            loadW(it + 1);
        }
        __syncthreads();

        const u32 sX = smaddr(Xst);
        const u32 sW = smaddr(Wst);
        #pragma unroll
        for (int k4 = 0; k4 < 4; k4++) {
            u32 ah[4];
            ldsm4(ah, sX + 2*(arow*PSTR + k4*16 + acol));
            #pragma unroll
            for (int w = 0; w < 3; w++) {
                #pragma unroll
                for (int npl = 0; npl < 2; npl++) {
                    int np = nhalf*2 + npl;
                    u32 bh[4];
                    u32 off = sW + 2*(u32)(w*64*PSTR + (k4*16 + trow)*PSTR + np*16 + tcol);
                    ldsm4t(bh, off);
                    mmaf(acc[w][2*npl],   ah, bh[0], bh[1]);
                    mmaf(acc[w][2*npl+1], ah, bh[2], bh[3]);
                }
            }
        }
        __syncthreads();
    }

    const float qs = 0.125f * 1.4426950408889634f;
    const int lrow = wm + (lane >> 2);
    const int r0 = m0 + lrow;
    const int cc = (lane & 3) * 2;
    #pragma unroll
    for (int w = 0; w < 3; w++) {
        u16* gh = (w == 0) ? g_q16 : ((w == 1) ? g_k16 : g_v16);
        const float s = (w == 0) ? qs : 1.0f;
        #pragma unroll
        for (int jl = 0; jl < 4; jl++) {
            int jg = 4*nhalf + jl;
            if (lrow < nrows)
                *reinterpret_cast<u32*>(&gh[(size_t)r0*D_ + jg*8 + cc]) =
                    pack2h(acc[w][jl][0]*s, acc[w][jl][1]*s);
            if (lrow + 8 < nrows)
                *reinterpret_cast<u32*>(&gh[(size_t)(r0+8)*D_ + jg*8 + cc]) =
                    pack2h(acc[w][jl][2]*s, acc[w][jl][3]*s);
        }
    }
}

// ---------------------------------------------------------------------------
// Kernel 2: fp16 HMMA flash attention, 2 CTAs/SM + TILE-ORDER ROTATION.
// Each CTA processes tiles in order kt = (16*(bid&3) + i) mod 64, so
// co-resident CTAs sit in different compute phases (MMA vs MUFU/pack) and
// their pipe usage overlaps instead of phase-locking.
// 64 q-rows/CTA, grid (64,4), block 256 = 4 qg(16 rows) x 2 khalf.
// 4-stage ring keyed by sequence index i, 1 barrier/tile, Q parks in stage 3.
// ---------------------------------------------------------------------------
#define ASTR 72
#define KV_U16 (2*64*ASTR)   // u16 per stage (18432 B)
#define NSTG 4
#define LOG2_SHIFT 12.0f

__global__ __launch_bounds__(256, 2) void attn(float* __restrict__ out)
{
    extern __shared__ u16 sma[];   // 4 stages; reused as float Obuf at the end

    const int tid  = threadIdx.x;
    const int lane = tid & 31;
    const int wid  = tid >> 5;
    const int khalf = (wid >= 4) ? 1 : 0;   // key half (32 keys)
    const int qg    = wid - khalf*4;        // q-row group (16 rows)
    const int bq0   = blockIdx.y * T_ + blockIdx.x * 64;
    const int b     = blockIdx.y;
    const int toff  = (blockIdx.x & 3) * 16;   // phase rotation (4 groups)

    const size_t bbase = (size_t)b * T_ * D_;
    // i = sequence index; actual tile = (toff + i) & 63; stage = i & 3.
    auto issueKV = [&](int i){
        const int kt = (toff + i) & 63;
        const u32 stb = smaddr(sma + (i & 3)*KV_U16);
        const size_t kbase = bbase + (size_t)kt*64*D_;
        #pragma unroll
        for (int t = 0; t < 4; t++) {
            int id = tid + t*256;        // 1024 chunks exactly
            int a   = id >> 9;           // 0 = K, 1 = V
            int rem = id & 511;
            int r  = rem >> 3;
            int ch = rem & 7;
            const u16* g = a ? g_v16 : g_k16;
            const u16* src = g + kbase + (size_t)r*D_ + ch*8;
            u32 dst = stb + 2*(u32)(a*64*ASTR + r*ASTR + ch*8);
            CP16(dst, src);
        }
    };

    // Prologue: sequence tiles 0,1,2 into stages 0,1,2.
    issueKV(0); CPCOMMIT();
    issueKV(1); CPCOMMIT();
    issueKV(2); CPCOMMIT();

    // Q parks in stage 3 (sequence tile 3 lands there only after the first
    // loop barrier, which every thread passes only after its Q ldsm is done).
    u16* Qsm = sma + 3*KV_U16;
    #pragma unroll
    for (int t = 0; t < 2; t++) {
        int id = tid + t * 256;          // 64 rows x 8 chunks = 512 exactly
        int r = id >> 3, cc = id & 7;
        *reinterpret_cast<uint4*>(&Qsm[r*ASTR + cc*8]) =
            *reinterpret_cast<const uint4*>(&g_q16[(size_t)(bq0 + r)*D_ + cc*8]);
    }
    __syncthreads();

    const int acol = ((lane >> 4) << 3);
    const int arow = qg*16 + (lane & 15);
    u32 qf[4][4];
    {
        const u32 sQ = smaddr(Qsm);
        #pragma unroll
        for (int k4 = 0; k4 < 4; k4++)
            ldsm4(qf[k4], sQ + 2*(arow*ASTR + k4*16 + acol));
    }

    const int brow = (lane & 7) + ((lane >> 4) << 3);
    const int bcol = (lane & 8);
    const int vrow = (lane & 15);
    const int vcol = ((lane >> 4) << 3);
    const int kofs = khalf * 32;

    float o[8][4];
    #pragma unroll
    for (int j = 0; j < 8; j++)
        #pragma unroll
        for (int q = 0; q < 4; q++) o[j][q] = 0.f;
    float rs0 = 0.f, rs1 = 0.f;

    const int nT = T_/64;
    for (int i = 0; i < nT; i++) {
        const int st = i & 3;
        if (i < nT - 2)      { CPWAIT(2); }
        else if (i == nT-2)  { CPWAIT(1); }
        else                 { CPWAIT(0); }
        __syncthreads();
        if (i + 3 < nT) { issueKV(i + 3); CPCOMMIT(); }

        const u32 stb = smaddr(sma + st*KV_U16);
        const u32 sK = stb;
        const u32 sV = stb + 2*(64*ASTR);

        // ---- S = Q @ K^T (this warp's 32-key half) ----
        float sc[4][4];
        #pragma unroll
        for (int j = 0; j < 4; j++)
            #pragma unroll
            for (int q = 0; q < 4; q++) sc[j][q] = 0.f;

        #pragma unroll
        for (int k4 = 0; k4 < 4; k4++) {
            #pragma unroll
            for (int np = 0; np < 2; np++) {
                u32 bh[4];
                ldsm4(bh, sK + 2*(u32)((kofs + np*16 + brow)*ASTR + k4*16 + bcol));
                mmaf(sc[2*np],   qf[k4], bh[0], bh[1]);
                mmaf(sc[2*np+1], qf[k4], bh[2], bh[3]);
            }
        }

        // ---- exp2 (shifted), partial row sums, pack P ----
        #pragma unroll
        for (int j = 0; j < 4; j++) {
            #pragma unroll
            for (int q = 0; q < 4; q++) sc[j][q] = ex2f(sc[j][q] - LOG2_SHIFT);
            rs0 += sc[j][0] + sc[j][1];
            rs1 += sc[j][2] + sc[j][3];
        }
        u32 pf[2][4];
        #pragma unroll
        for (int k2 = 0; k2 < 2; k2++) {
            pf[k2][0] = pack2h(sc[2*k2][0],   sc[2*k2][1]);
            pf[k2][1] = pack2h(sc[2*k2][2],   sc[2*k2][3]);
            pf[k2][2] = pack2h(sc[2*k2+1][0], sc[2*k2+1][1]);
            pf[k2][3] = pack2h(sc[2*k2+1][2], sc[2*k2+1][3]);
        }

        // ---- O += P @ V (over this warp's 32 keys) ----
        #pragma unroll
        for (int k2 = 0; k2 < 2; k2++) {
            #pragma unroll
            for (int np = 0; np < 4; np++) {
                u32 bh[4];
                ldsm4t(bh, sV + 2*(u32)((kofs + k2*16 + vrow)*ASTR + np*16 + vcol));
                mmaf(o[2*np],   pf[k2], bh[0], bh[1]);
                mmaf(o[2*np+1], pf[k2], bh[2], bh[3]);
            }
        }
    }

    // ---- combine the two key-halves ----
    rs0 += __shfl_xor_sync(0xffffffffu, rs0, 1);
    rs0 += __shfl_xor_sync(0xffffffffu, rs0, 2);
    rs1 += __shfl_xor_sync(0xffffffffu, rs1, 1);
    rs1 += __shfl_xor_sync(0xffffffffu, rs1, 2);

    __syncthreads();   // all stage reads done before smem reuse as Obuf
    float* Ob  = reinterpret_cast<float*>(sma);      // [64][68]
    float* rsb = Ob + 64*68;                         // [64]
    const int row0 = qg*16 + (lane >> 2);
    const int cc = (lane & 3) * 2;

    if (khalf == 0) {
        #pragma unroll
        for (int j = 0; j < 8; j++) {
            Ob[row0*68 + j*8 + cc]         = o[j][0];
            Ob[row0*68 + j*8 + cc + 1]     = o[j][1];
            Ob[(row0+8)*68 + j*8 + cc]     = o[j][2];
            Ob[(row0+8)*68 + j*8 + cc + 1] = o[j][3];
        }
        if ((lane & 3) == 0) { rsb[row0] = rs0; rsb[row0+8] = rs1; }
    }
    __syncthreads();
    if (khalf == 1) {
        const float i0 = 1.f / (rs0 + rsb[row0]);
        const float i1 = 1.f / (rs1 + rsb[row0+8]);
        const int r0 = bq0 + row0;
        #pragma unroll
        for (int j = 0; j < 8; j++) {
            float2 v0 = make_float2((o[j][0] + Ob[row0*68 + j*8 + cc]) * i0,
                                    (o[j][1] + Ob[row0*68 + j*8 + cc + 1]) * i0);
            float2 v1 = make_float2((o[j][2] + Ob[(row0+8)*68 + j*8 + cc]) * i1,
                                    (o[j][3] + Ob[(row0+8)*68 + j*8 + cc + 1]) * i1);
            *reinterpret_cast<float2*>(&out[(size_t)r0*D_ + j*8 + cc]) = v0;
            *reinterpret_cast<float2*>(&out[(size_t)(r0+8)*D_ + j*8 + cc]) = v1;
        }
    }
}

// ---------------------------------------------------------------------------

extern "C" void kernel_launch(void* const* d_in, const int* in_sizes, int n_in,
                              void* d_out, int out_size)
{
    const float* x  = (const float*)d_in[0];
    const float* Wq = (const float*)d_in[1];
    const float* Wk = (const float*)d_in[2];
    const float* Wv = (const float*)d_in[3];
    float* out = (float*)d_out;

    const int proj_smem = (2*X_STAGE + 2*W_STAGE) * (int)sizeof(u16);   // 87552
    cudaFuncSetAttribute(proj, cudaFuncAttributeMaxDynamicSharedMemorySize, proj_smem);
    proj<<<dim3(GX, B_), 448, proj_smem>>>(x, Wq, Wk, Wv);

    const int attn_smem = NSTG*KV_U16 * (int)sizeof(u16);               // 73728
    cudaFuncSetAttribute(attn, cudaFuncAttributeMaxDynamicSharedMemorySize, attn_smem);
    attn<<<dim3(64, B_), 256, attn_smem>>>(out);
}